// round 15
// baseline (speedup 1.0000x reference)
#include <cuda_runtime.h>
#include <cuda_bf16.h>
#include <math.h>

#define NN 2048
#define BB 32
#define NSTEPS 10
#define KSPLIT 8
#define KC 256                // tracked neurons / B cols per CTA
#define MT 128                // produced rows per CTA (MMA tile)
#define CTAS 128
#define THREADS 256
#define SSTR 264              // smem row stride (bf16 elems)
#define SA_ELEMS (MT * SSTR)
#define SB_ELEMS (64 * SSTR)
#define SMEM_B_OFF (SA_ELEMS * 2)
#define SMEM_TH_OFF (SMEM_B_OFF + SB_ELEMS * 2)
#define SMEM_OM_OFF (SMEM_TH_OFF + 8192 * 4)
#define SMEM_RED_OFF (SMEM_OM_OFF + 256 * 4)
#define SMEM_BYTES (SMEM_RED_OFF + 64 * 4)

// Persistent scratch (no allocations allowed)
__device__ __align__(16) float g_ps[3][KSPLIT][BB * NN];   // partials K*sin [col][row]
__device__ __align__(16) float g_pc[3][KSPLIT][BB * NN];   // partials K*cos
__device__ __align__(16) float2 g_cohP[BB * 8];
__device__ __align__(16) float g_theta_fallback[BB * NN];
__device__ __align__(128) unsigned g_flagP[CTAS * 32];     // one 128B line per CTA
__device__ __align__(128) unsigned g_cnt;
__device__ __align__(128) unsigned g_gen;

// Full-grid barrier (prologue/epilogue only).
static __device__ __forceinline__ void gbar() {
    __syncthreads();
    if (threadIdx.x == 0) {
        unsigned my;
        asm volatile("ld.acquire.gpu.global.u32 %0, [%1];"
                     : "=r"(my) : "l"(&g_gen) : "memory");
        __threadfence();
        unsigned arr = atomicAdd(&g_cnt, 1u);
        if (arr == CTAS - 1) {
            g_cnt = 0;
            asm volatile("red.release.gpu.global.add.u32 [%0], %1;"
                         :: "l"(&g_gen), "r"(1u) : "memory");
        } else {
            unsigned v;
            do {
                __nanosleep(64);
                asm volatile("ld.acquire.gpu.global.u32 %0, [%1];"
                             : "=r"(v) : "l"(&g_gen) : "memory");
            } while (v == my);
        }
        __threadfence();
    }
    __syncthreads();
}

// Warp-collective poll: lanes with `need` poll *addr until >= target.
static __device__ __forceinline__ void poll_ge(const unsigned* addr,
                                               unsigned target, bool need) {
    for (;;) {
        unsigned x = target;
        if (need)
            asm volatile("ld.acquire.gpu.global.u32 %0, [%1];"
                         : "=r"(x) : "l"(addr) : "memory");
        if (__all_sync(0xffffffffu, x >= target)) break;
        __nanosleep(20);
    }
}

// CTA-level signal: stores -> fence -> bar -> single release-increment.
static __device__ __forceinline__ void signalC(unsigned* flag, int tid) {
    __threadfence();
    __syncthreads();
    if (tid == 0)
        asm volatile("red.release.gpu.global.add.u32 [%0], %1;"
                     :: "l"(flag), "r"(1u) : "memory");
}

__global__ void __launch_bounds__(THREADS, 1)
k_all(const float* __restrict__ theta_in, const float* __restrict__ K,
      const float* __restrict__ omega, const float* __restrict__ Kg,
      const float* __restrict__ mu, float* __restrict__ th_out,
      float* __restrict__ coh_out) {
    extern __shared__ __align__(16) char smem_raw[];
    __nv_bfloat16* sA = (__nv_bfloat16*)smem_raw;               // resident K tile
    __nv_bfloat16* sB = (__nv_bfloat16*)(smem_raw + SMEM_B_OFF); // sin/cos tile
    float* sTheta = (float*)(smem_raw + SMEM_TH_OFF);           // 32 batch x 256 rows
    float* sOmega = (float*)(smem_raw + SMEM_OM_OFF);
    float* sRed   = (float*)(smem_raw + SMEM_RED_OFF);

    int tid  = threadIdx.x;
    int lane = tid & 31;
    int w    = tid >> 5;
    int bid  = blockIdx.x;
    int ib   = bid >> 3, ks = bid & 7;
    int i0   = ib * MT, k0 = ks * KC;
    int g    = lane >> 2, t4 = lane & 3;

    // tracked-slice mapping for update: batch bq, rows rblk*32..+32 of [k0,+256)
    int bq   = tid >> 3;
    int rblk = tid & 7;

    // ---- prologue ----
    if (tid == 0) g_flagP[bid * 32] = 0u;
    {   // A tile: K[i0.., k0..] fp32 -> bf16 smem
        const float* Kt = K + (size_t)i0 * NN + k0;
#pragma unroll 4
        for (int it = 0; it < 32; it++) {
            int idx = it * THREADS + tid;
            int row = idx >> 6, c = idx & 63;
            float4 v = *(const float4*)(Kt + (size_t)row * NN + c * 4);
            __nv_bfloat162 lo = __floats2bfloat162_rn(v.x, v.y);
            __nv_bfloat162 hi = __floats2bfloat162_rn(v.z, v.w);
            uint2 pk = make_uint2(*(unsigned*)&lo, *(unsigned*)&hi);
            *(uint2*)(sA + row * SSTR + c * 4) = pk;
        }
    }
    // theta slice: all 32 batches x rows [k0, k0+256)
#pragma unroll
    for (int it = 0; it < 8; it++) {
        int e4 = it * THREADS + tid;          // 2048 float4
        int b  = e4 >> 6, r = (e4 & 63) * 4;
        *(float4*)&sTheta[b * 256 + r] =
            *(const float4*)&theta_in[(size_t)b * NN + k0 + r];
    }
    if (tid < 64)
        *(float4*)&sOmega[tid * 4] = *(const float4*)&omega[k0 + tid * 4];
    float coef = (Kg[0] * (1.0f / NN)) * (mu[0] * 0.5f);
    __syncthreads();
    // initial bf16 sin/cos -> sB (accurate seed)
#pragma unroll 2
    for (int q = 0; q < 8; q++) {
        int row = rblk * 32 + q * 4;
        float4 th = *(float4*)&sTheta[bq * 256 + row];
        float s0, c0, s1, c1, s2, c2, s3, c3;
        sincosf(th.x, &s0, &c0); sincosf(th.y, &s1, &c1);
        sincosf(th.z, &s2, &c2); sincosf(th.w, &s3, &c3);
        __nv_bfloat162 sA_ = __floats2bfloat162_rn(s0, s1);
        __nv_bfloat162 sBp = __floats2bfloat162_rn(s2, s3);
        __nv_bfloat162 cA_ = __floats2bfloat162_rn(c0, c1);
        __nv_bfloat162 cBp = __floats2bfloat162_rn(c2, c3);
        *(__nv_bfloat162*)&sB[bq * SSTR + row]            = sA_;
        *(__nv_bfloat162*)&sB[bq * SSTR + row + 2]        = sBp;
        *(__nv_bfloat162*)&sB[(32 + bq) * SSTR + row]     = cA_;
        *(__nv_bfloat162*)&sB[(32 + bq) * SSTR + row + 2] = cBp;
    }
    gbar();

    int b_nt_off = (lane >> 4);
    int b_khalf  = ((lane >> 3) & 1) * 8;
    int b_rowin  = lane & 7;

    // ---- steps: [update (t>0)] -> MMA -> store partials -> signal ----
    for (int t = 0; t <= NSTEPS; t++) {
        if (t > 0) {
            // ONE hop: poll the 16 producers of rows [k0,+256) for step t-1
            if (w == 0) {
                const unsigned* a =
                    &g_flagP[((2 * ks + (lane >> 3)) * 8 + (lane & 7)) * 32];
                poll_ge(a, (unsigned)t, lane < 16);
            }
            __syncthreads();
            int rb = (t - 1) % 3;
#pragma unroll 2
            for (int q = 0; q < 8; q++) {
                int row = rblk * 32 + q * 4;
                size_t off = (size_t)bq * NN + k0 + row;
                float4 ss = make_float4(0.f, 0.f, 0.f, 0.f);
                float4 cs = make_float4(0.f, 0.f, 0.f, 0.f);
#pragma unroll
                for (int kq = 0; kq < KSPLIT; kq++) {
                    float4 p = *(const float4*)&g_ps[rb][kq][off];
                    ss.x += p.x; ss.y += p.y; ss.z += p.z; ss.w += p.w;
                    float4 pq = *(const float4*)&g_pc[rb][kq][off];
                    cs.x += pq.x; cs.y += pq.y; cs.z += pq.z; cs.w += pq.w;
                }
                float4 th = *(float4*)&sTheta[bq * 256 + row];
                float4 om = *(float4*)&sOmega[row];
                __nv_bfloat162 s01 = *(__nv_bfloat162*)&sB[bq * SSTR + row];
                __nv_bfloat162 s23 = *(__nv_bfloat162*)&sB[bq * SSTR + row + 2];
                __nv_bfloat162 c01 = *(__nv_bfloat162*)&sB[(32 + bq) * SSTR + row];
                __nv_bfloat162 c23 = *(__nv_bfloat162*)&sB[(32 + bq) * SSTR + row + 2];
                float2 sl = __bfloat1622float2(s01), sh = __bfloat1622float2(s23);
                float2 cl = __bfloat1622float2(c01), ch = __bfloat1622float2(c23);
                th.x = fmaf(0.1f, om.x + coef * (cl.x * ss.x - sl.x * cs.x), th.x);
                th.y = fmaf(0.1f, om.y + coef * (cl.y * ss.y - sl.y * cs.y), th.y);
                th.z = fmaf(0.1f, om.z + coef * (ch.x * ss.z - sh.x * cs.z), th.z);
                th.w = fmaf(0.1f, om.w + coef * (ch.y * ss.w - sh.y * cs.w), th.w);
                *(float4*)&sTheta[bq * 256 + row] = th;
                if (t < NSTEPS) {
                    float s0, c0, s1, c1, s2, c2, s3, c3;
                    __sincosf(th.x, &s0, &c0); __sincosf(th.y, &s1, &c1);
                    __sincosf(th.z, &s2, &c2); __sincosf(th.w, &s3, &c3);
                    *(__nv_bfloat162*)&sB[bq * SSTR + row] =
                        __floats2bfloat162_rn(s0, s1);
                    *(__nv_bfloat162*)&sB[bq * SSTR + row + 2] =
                        __floats2bfloat162_rn(s2, s3);
                    *(__nv_bfloat162*)&sB[(32 + bq) * SSTR + row] =
                        __floats2bfloat162_rn(c0, c1);
                    *(__nv_bfloat162*)&sB[(32 + bq) * SSTR + row + 2] =
                        __floats2bfloat162_rn(c2, c3);
                }
            }
            __syncthreads();
        }
        if (t == NSTEPS) break;

        // MMA: rows [i0,+128) x 64 cols x k [k0,+256) (R13-proven fragments)
        float acc[8][4];
#pragma unroll
        for (int nt = 0; nt < 8; nt++)
#pragma unroll
            for (int r = 0; r < 4; r++) acc[nt][r] = 0.f;

#pragma unroll 4
        for (int kk = 0; kk < KC; kk += 16) {
            unsigned a0, a1, a2, a3;
            const __nv_bfloat16* ap =
                sA + (w * 16 + (lane & 15)) * SSTR + kk + ((lane >> 4) * 8);
            unsigned sa_ = (unsigned)__cvta_generic_to_shared(ap);
            asm volatile(
                "ldmatrix.sync.aligned.m8n8.x4.shared.b16 {%0,%1,%2,%3}, [%4];"
                : "=r"(a0), "=r"(a1), "=r"(a2), "=r"(a3) : "r"(sa_));
#pragma unroll
            for (int ntp = 0; ntp < 4; ntp++) {
                int nt0 = 2 * ntp;
                const __nv_bfloat16* bp =
                    sB + ((nt0 + b_nt_off) * 8 + b_rowin) * SSTR + kk + b_khalf;
                unsigned sb_ = (unsigned)__cvta_generic_to_shared(bp);
                unsigned b0, b1, b2, b3;
                asm volatile(
                    "ldmatrix.sync.aligned.m8n8.x4.shared.b16 {%0,%1,%2,%3}, [%4];"
                    : "=r"(b0), "=r"(b1), "=r"(b2), "=r"(b3) : "r"(sb_));
                asm volatile(
                    "mma.sync.aligned.m16n8k16.row.col.f32.bf16.bf16.f32 "
                    "{%0,%1,%2,%3}, {%4,%5,%6,%7}, {%8,%9}, {%0,%1,%2,%3};"
                    : "+f"(acc[nt0][0]), "+f"(acc[nt0][1]),
                      "+f"(acc[nt0][2]), "+f"(acc[nt0][3])
                    : "r"(a0), "r"(a1), "r"(a2), "r"(a3), "r"(b0), "r"(b1));
                asm volatile(
                    "mma.sync.aligned.m16n8k16.row.col.f32.bf16.bf16.f32 "
                    "{%0,%1,%2,%3}, {%4,%5,%6,%7}, {%8,%9}, {%0,%1,%2,%3};"
                    : "+f"(acc[nt0 + 1][0]), "+f"(acc[nt0 + 1][1]),
                      "+f"(acc[nt0 + 1][2]), "+f"(acc[nt0 + 1][3])
                    : "r"(a0), "r"(a1), "r"(a2), "r"(a3), "r"(b2), "r"(b3));
            }
        }

        // store partials (cols 0-31 sin, 32-63 cos) to buffer t%3
        {
            int wb = t % 3;
            int ir = i0 + w * 16 + g;
#pragma unroll
            for (int nt = 0; nt < 8; nt++) {
                int col = nt * 8 + 2 * t4;
                float* dst = (nt < 4) ? g_ps[wb][ks] : g_pc[wb][ks];
                int cb = col & 31;
                dst[(size_t)cb * NN + ir]           = acc[nt][0];
                dst[(size_t)(cb + 1) * NN + ir]     = acc[nt][1];
                dst[(size_t)cb * NN + ir + 8]       = acc[nt][2];
                dst[(size_t)(cb + 1) * NN + ir + 8] = acc[nt][3];
            }
        }
        signalC(&g_flagP[bid * 32], tid);   // flag value becomes t+1
    }

    // ---- epilogue: wrap + output (CTA writes batches {2ib, 2ib+1}) ----
    int b  = 2 * ib + (tid >> 7);
    int r  = (tid & 127) * 2;
    float th0 = sTheta[b * 256 + r];
    float th1 = sTheta[b * 256 + r + 1];
    float sn0, cn0, sn1, cn1;
    sincosf(th0, &sn0, &cn0);
    sincosf(th1, &sn1, &cn1);
    th_out[(size_t)b * NN + k0 + r]     = atan2f(sn0, cn0);  // wrap (-pi,pi]
    th_out[(size_t)b * NN + k0 + r + 1] = atan2f(sn1, cn1);

    if (coh_out) {
        // sin/cos of wrapped == sin/cos of unwrapped
        float ssP = sn0 + sn1, ccP = cn0 + cn1;
#pragma unroll
        for (int o = 16; o > 0; o >>= 1) {
            ssP += __shfl_xor_sync(0xffffffffu, ssP, o);
            ccP += __shfl_xor_sync(0xffffffffu, ccP, o);
        }
        if (lane == 0) { sRed[w * 2] = ssP; sRed[w * 2 + 1] = ccP; }
        __syncthreads();
        if (tid == 0 || tid == 128) {
            int wb = (tid >> 7) * 4;
            float ss = sRed[wb*2] + sRed[wb*2+2] + sRed[wb*2+4] + sRed[wb*2+6];
            float cc = sRed[wb*2+1] + sRed[wb*2+3] + sRed[wb*2+5] + sRed[wb*2+7];
            g_cohP[b * 8 + ks] = make_float2(ss, cc);
        }
        gbar();
        if (bid < BB) {            // CTA bid finalizes batch bid
            float ss = 0.f, cc = 0.f;
            if (tid == 0) {
#pragma unroll
                for (int q = 0; q < 8; q++) {
                    float2 p = g_cohP[bid * 8 + q];
                    ss += p.x; cc += p.y;
                }
                float sm = ss * (1.0f / NN), cm = cc * (1.0f / NN);
                coh_out[bid] = sqrtf(cm * cm + sm * sm);
            }
        }
    }
}

extern "C" void kernel_launch(void* const* d_in, const int* in_sizes, int n_in,
                              void* d_out, int out_size) {
    const float* theta = (const float*)d_in[0];
    const float* K     = (const float*)d_in[1];
    const float* omega = (const float*)d_in[2];
    const float* Kg    = (const float*)d_in[3];
    const float* mu    = (const float*)d_in[4];
    float* out = (float*)d_out;

    float* th_buf;
    float* coh_out = nullptr;
    if (out_size >= BB * NN) {
        th_buf = out;
        if (out_size >= BB * NN + BB) coh_out = out + BB * NN;
    } else {
        float* sym;
        cudaGetSymbolAddress((void**)&sym, g_theta_fallback);
        th_buf = sym;
        coh_out = out;
    }

    cudaFuncSetAttribute(k_all, cudaFuncAttributeMaxDynamicSharedMemorySize,
                         SMEM_BYTES);
    k_all<<<CTAS, THREADS, SMEM_BYTES>>>(theta, K, omega, Kg, mu,
                                         th_buf, coh_out);
}

// round 16
// speedup vs baseline: 3.6913x; 3.6913x over previous
#include <cuda_runtime.h>
#include <cuda_bf16.h>
#include <math.h>

#define NN 2048
#define BB 32
#define NSTEPS 10
#define KSPLIT 8
#define KC 256                // K chunk per CTA
#define MT 128                // rows per CTA (MMA tile)
#define CTAS 128
#define THREADS 256
#define SSTR 264              // smem row stride (bf16 elems)
#define SA_ELEMS (MT * SSTR)
#define SB_ELEMS (64 * SSTR)
#define SMEM_BYTES ((SA_ELEMS + SB_ELEMS) * 2)

// Persistent scratch (no allocations allowed)
__device__ __align__(16) __nv_bfloat16 g_SCb[3][64 * NN];  // triple-buffered sin/cos
__device__ __align__(16) float g_ps[2][KSPLIT][BB * NN];   // partials K*sin [col][row]
__device__ __align__(16) float g_pc[2][KSPLIT][BB * NN];   // partials K*cos
__device__ __align__(16) float2 g_cohP[CTAS * BB];
__device__ __align__(16) float g_theta_fallback[BB * NN];
// Monotonic flags (NEVER reset; base re-read each launch).
// flagP: per-warp producer flags [ib][producer ks][warp w]
__device__ __align__(128) unsigned g_flagP[16 * 64];
// flagU: per-warp update flags [ib][ks][warp w] (warp w owns batches 4w..4w+3)
__device__ __align__(128) unsigned g_flagU[16 * 64];
// flagC: per-CTA coherence-partial flags, one 128B line per CTA
__device__ __align__(128) unsigned g_flagC[CTAS * 32];

static __device__ __forceinline__ void cp16(void* dst_smem, const void* src) {
    unsigned d = (unsigned)__cvta_generic_to_shared(dst_smem);
    asm volatile("cp.async.cg.shared.global [%0], [%1], 16;\n" :: "r"(d), "l"(src));
}
static __device__ __forceinline__ void cp_commit() {
    asm volatile("cp.async.commit_group;\n");
}
template <int N>
static __device__ __forceinline__ void cp_wait() {
    asm volatile("cp.async.wait_group %0;\n" :: "n"(N));
}

static __device__ __forceinline__ unsigned ld_acq(const unsigned* a) {
    unsigned v;
    asm volatile("ld.acquire.gpu.global.u32 %0, [%1];"
                 : "=r"(v) : "l"(a) : "memory");
    return v;
}

// Warp-collective poll: lanes with `need` poll *addr until >= target.
static __device__ __forceinline__ void poll_ge(const unsigned* addr,
                                               unsigned target, bool need) {
    for (;;) {
        unsigned x = target;
        if (need) x = ld_acq(addr);
        if (__all_sync(0xffffffffu, x >= target)) break;
        __nanosleep(20);
    }
}

// Warp-level signal: this warp's stores -> syncwarp -> lane0 release-inc.
static __device__ __forceinline__ void signal_warp(unsigned* flag, int lane) {
    __syncwarp();
    if (lane == 0)
        asm volatile("red.release.gpu.global.add.u32 [%0], %1;"
                     :: "l"(flag), "r"(1u) : "memory");
}

// CTA-level signal: stores -> fence -> bar -> single release-increment.
static __device__ __forceinline__ void signalC(unsigned* flag, int tid) {
    __threadfence();
    __syncthreads();
    if (tid == 0)
        asm volatile("red.release.gpu.global.add.u32 [%0], %1;"
                     :: "l"(flag), "r"(1u) : "memory");
}

__global__ void __launch_bounds__(THREADS, 1)
k_all(const float* __restrict__ theta_in, const float* __restrict__ K,
      const float* __restrict__ omega, const float* __restrict__ Kg,
      const float* __restrict__ mu, float* __restrict__ th_out,
      float* __restrict__ coh_out) {
    extern __shared__ __align__(16) char smem_raw[];
    __nv_bfloat16* sA = (__nv_bfloat16*)smem_raw;        // resident K tile
    __nv_bfloat16* sB = sA + SA_ELEMS;                   // per-step sin/cos tile

    int tid  = threadIdx.x;
    int lane = tid & 31;
    int w    = tid >> 5;
    int bid  = blockIdx.x;
    int ib   = bid >> 3, ks = bid & 7;
    int i0   = ib * MT, k0 = ks * KC;
    int g    = lane >> 2, t4 = lane & 3;

    // update-slice mapping: this CTA updates rows [i0 + 16*ks, +16) x 32 batches
    int bb   = tid >> 3;                       // batch 0..31 (warp w: 4w..4w+3)
    int rloc = (tid & 7) * 2;                  // local row pair
    int irow = i0 + ks * 16 + rloc;
    int eidx = bb * NN + irow;

    // ---- flag bases: read OWN slots before any signal this launch.
    // Launch boundary is the global sync; all flags of a class share one
    // per-launch count (flagU: 10, flagP: 10, flagC: 1), so own value == base.
    unsigned base_u = ld_acq(&g_flagU[ib * 64 + ks * 8 + w]);
    unsigned base_p = ld_acq(&g_flagP[ib * 64 + ks * 8 + w]);
    unsigned base_c = ld_acq(&g_flagC[bid * 32]);

    // ---- prologue: convert K tile, seed state ----
    {
        const float* Kt = K + (size_t)i0 * NN + k0;
#pragma unroll 4
        for (int it = 0; it < 32; it++) {
            int idx = it * THREADS + tid;           // 8192 float4
            int row = idx >> 6, c = idx & 63;
            float4 v = *(const float4*)(Kt + (size_t)row * NN + c * 4);
            __nv_bfloat162 lo = __floats2bfloat162_rn(v.x, v.y);
            __nv_bfloat162 hi = __floats2bfloat162_rn(v.z, v.w);
            uint2 pk = make_uint2(*(unsigned*)&lo, *(unsigned*)&hi);
            *(uint2*)(sA + row * SSTR + c * 4) = pk;
        }
    }
    float th0 = theta_in[eidx], th1 = theta_in[eidx + 1];
    float om0 = omega[irow],    om1 = omega[irow + 1];
    float coef = (Kg[0] * (1.0f / NN)) * (mu[0] * 0.5f);
    float s0, c0, s1, c1;
    sincosf(th0, &s0, &c0);    // one-time accurate seed
    sincosf(th1, &s1, &c1);
    __nv_bfloat162 sb2 = __floats2bfloat162_rn(s0, s1);
    __nv_bfloat162 cb2 = __floats2bfloat162_rn(c0, c1);
    *(__nv_bfloat162*)&g_SCb[0][eidx]           = sb2;
    *(__nv_bfloat162*)&g_SCb[0][32 * NN + eidx] = cb2;
    float si0 = __low2float(sb2), si1 = __high2float(sb2);
    float ci0 = __low2float(cb2), ci1 = __high2float(cb2);
    // Seed publication = flagU signal #1 (warp w owns batches 4w..4w+3).
    signal_warp(&g_flagU[ib * 64 + ks * 8 + w], lane);

    // ---- 10 steps ----
    for (int step = 0; step < NSTEPS; step++) {
        int par  = step & 1;        // partials parity
        int par3 = step % 3;        // g_SCb read buffer
        const __nv_bfloat16* Bsrc = g_SCb[par3];

        // Per-warp pipelined hopU: warp w handles batch-group w.
        // flagU target: seed(1) + updates of steps 0..step-1 => base_u+step+1.
        {
            const unsigned* a = (lane < 8)
                ? &g_flagU[(2 * ks) * 64 + lane * 8 + w]
                : &g_flagU[(2 * ks + 1) * 64 + (lane - 8) * 8 + w];
            poll_ge(a, base_u + (unsigned)step + 1u, lane < 16);
#pragma unroll
            for (int it = 0; it < 8; it++) {
                int row = (it < 4) ? (4 * w + it) : (32 + 4 * w + (it - 4));
                cp16(sB + row * SSTR + lane * 8,
                     Bsrc + (size_t)row * NN + k0 + lane * 8);
            }
            cp_commit();
            cp_wait<0>();
        }
        __syncthreads();

        float acc[8][4];
#pragma unroll
        for (int nt = 0; nt < 8; nt++)
#pragma unroll
            for (int r = 0; r < 4; r++) acc[nt][r] = 0.f;

        int b_nt_off = (lane >> 4);
        int b_khalf  = ((lane >> 3) & 1) * 8;
        int b_rowin  = lane & 7;

#pragma unroll 4
        for (int kk = 0; kk < KC; kk += 16) {
            unsigned a0, a1, a2, a3;
            const __nv_bfloat16* ap =
                sA + (w * 16 + (lane & 15)) * SSTR + kk + ((lane >> 4) * 8);
            unsigned sa = (unsigned)__cvta_generic_to_shared(ap);
            asm volatile(
                "ldmatrix.sync.aligned.m8n8.x4.shared.b16 {%0,%1,%2,%3}, [%4];"
                : "=r"(a0), "=r"(a1), "=r"(a2), "=r"(a3) : "r"(sa));
#pragma unroll
            for (int ntp = 0; ntp < 4; ntp++) {
                int nt0 = 2 * ntp;
                const __nv_bfloat16* bp =
                    sB + ((nt0 + b_nt_off) * 8 + b_rowin) * SSTR + kk + b_khalf;
                unsigned sb_ = (unsigned)__cvta_generic_to_shared(bp);
                unsigned b0, b1, b2, b3;
                asm volatile(
                    "ldmatrix.sync.aligned.m8n8.x4.shared.b16 {%0,%1,%2,%3}, [%4];"
                    : "=r"(b0), "=r"(b1), "=r"(b2), "=r"(b3) : "r"(sb_));
                asm volatile(
                    "mma.sync.aligned.m16n8k16.row.col.f32.bf16.bf16.f32 "
                    "{%0,%1,%2,%3}, {%4,%5,%6,%7}, {%8,%9}, {%0,%1,%2,%3};"
                    : "+f"(acc[nt0][0]), "+f"(acc[nt0][1]),
                      "+f"(acc[nt0][2]), "+f"(acc[nt0][3])
                    : "r"(a0), "r"(a1), "r"(a2), "r"(a3), "r"(b0), "r"(b1));
                asm volatile(
                    "mma.sync.aligned.m16n8k16.row.col.f32.bf16.bf16.f32 "
                    "{%0,%1,%2,%3}, {%4,%5,%6,%7}, {%8,%9}, {%0,%1,%2,%3};"
                    : "+f"(acc[nt0 + 1][0]), "+f"(acc[nt0 + 1][1]),
                      "+f"(acc[nt0 + 1][2]), "+f"(acc[nt0 + 1][3])
                    : "r"(a0), "r"(a1), "r"(a2), "r"(a3), "r"(b2), "r"(b3));
            }
        }

        // store partials (cols 0-31 sin, 32-63 cos), [col][row] layout;
        // each warp signals its per-warp flagP immediately after its stores.
        {
            int ir = i0 + w * 16 + g;
#pragma unroll
            for (int nt = 0; nt < 8; nt++) {
                int col = nt * 8 + 2 * t4;
                float* dst = (nt < 4) ? g_ps[par][ks] : g_pc[par][ks];
                int cb = col & 31;
                dst[(size_t)cb * NN + ir]           = acc[nt][0];
                dst[(size_t)(cb + 1) * NN + ir]     = acc[nt][1];
                dst[(size_t)cb * NN + ir + 8]       = acc[nt][2];
                dst[(size_t)(cb + 1) * NN + ir + 8] = acc[nt][3];
            }
        }
        signal_warp(&g_flagP[ib * 64 + ks * 8 + w], lane);   // signal #step+1

        // wait for warp-ks tiles of the 8 producer CTAs (group ib)
        if (w == 0) {
            const unsigned* a = &g_flagP[ib * 64 + (lane & 7) * 8 + ks];
            poll_ge(a, base_p + (unsigned)step + 1u, lane < 8);
        }
        __syncthreads();

        // update: reduce split-K partials, integrate
        float ss0 = 0.f, ss1 = 0.f, cs0 = 0.f, cs1 = 0.f;
#pragma unroll
        for (int kq = 0; kq < KSPLIT; kq++) {
            float2 p = *(const float2*)&g_ps[par][kq][eidx];
            ss0 += p.x; ss1 += p.y;
            float2 q = *(const float2*)&g_pc[par][kq][eidx];
            cs0 += q.x; cs1 += q.y;
        }
        th0 = fmaf(0.1f, om0 + coef * (ci0 * ss0 - si0 * cs0), th0);
        th1 = fmaf(0.1f, om1 + coef * (ci1 * ss1 - si1 * cs1), th1);

        if (step < NSTEPS - 1) {
            int wpar = (step + 1) % 3;
            __sincosf(th0, &s0, &c0);   // bf16 rounding dominates intrinsic err
            __sincosf(th1, &s1, &c1);
            sb2 = __floats2bfloat162_rn(s0, s1);
            cb2 = __floats2bfloat162_rn(c0, c1);
            *(__nv_bfloat162*)&g_SCb[wpar][eidx]           = sb2;
            *(__nv_bfloat162*)&g_SCb[wpar][32 * NN + eidx] = cb2;
            // flagU signal #step+2
            signal_warp(&g_flagU[ib * 64 + ks * 8 + w], lane);
            si0 = __low2float(sb2); si1 = __high2float(sb2);
            ci0 = __low2float(cb2); ci1 = __high2float(cb2);
        }
    }

    // ---- epilogue: reference-exact wrap (once), output, coherence ----
    float sn0, cn0, sn1, cn1;
    sincosf(th0, &sn0, &cn0); th0 = atan2f(sn0, cn0);
    sincosf(th1, &sn1, &cn1); th1 = atan2f(sn1, cn1);
    th_out[eidx]     = th0;
    th_out[eidx + 1] = th1;

    if (coh_out) {
        sincosf(th0, &sn0, &cn0);       // trig of wrapped theta (as reference)
        sincosf(th1, &sn1, &cn1);
        float ssP = sn0 + sn1, ccP = cn0 + cn1;
#pragma unroll
        for (int o = 4; o > 0; o >>= 1) {   // reduce 8-lane groups (same batch)
            ssP += __shfl_xor_sync(0xffffffffu, ssP, o);
            ccP += __shfl_xor_sync(0xffffffffu, ccP, o);
        }
        if ((lane & 7) == 0)
            g_cohP[bid * BB + bb] = make_float2(ssP, ccP);
    }
    // Always signal (keeps flagC count launch-invariant even if coh_out null).
    signalC(&g_flagC[bid * 32], tid);

    if (coh_out && bid < BB) {
        // Finalizer: warps 0-3 poll all 128 producers' flagC in parallel.
        if (w < 4)
            poll_ge(&g_flagC[(w * 32 + lane) * 32], base_c + 1u, true);
        __syncthreads();
        float* rs = (float*)smem_raw;
        float* rc = rs + THREADS;
        float ss = 0.f, cc = 0.f;
        if (tid < CTAS) {
            float2 p = g_cohP[tid * BB + bid];
            ss = p.x; cc = p.y;
        }
        rs[tid] = ss; rc[tid] = cc;
        __syncthreads();
        for (int o = 128; o > 0; o >>= 1) {
            if (tid < o) { rs[tid] += rs[tid + o]; rc[tid] += rc[tid + o]; }
            __syncthreads();
        }
        if (tid == 0) {
            float sm = rs[0] * (1.0f / NN), cm = rc[0] * (1.0f / NN);
            coh_out[bid] = sqrtf(cm * cm + sm * sm);
        }
    }
}

extern "C" void kernel_launch(void* const* d_in, const int* in_sizes, int n_in,
                              void* d_out, int out_size) {
    const float* theta = (const float*)d_in[0];
    const float* K     = (const float*)d_in[1];
    const float* omega = (const float*)d_in[2];
    const float* Kg    = (const float*)d_in[3];
    const float* mu    = (const float*)d_in[4];
    float* out = (float*)d_out;

    float* th_buf;
    float* coh_out = nullptr;
    if (out_size >= BB * NN) {
        th_buf = out;
        if (out_size >= BB * NN + BB) coh_out = out + BB * NN;
    } else {
        float* sym;
        cudaGetSymbolAddress((void**)&sym, g_theta_fallback);
        th_buf = sym;
        coh_out = out;
    }

    cudaFuncSetAttribute(k_all, cudaFuncAttributeMaxDynamicSharedMemorySize,
                         SMEM_BYTES);
    k_all<<<CTAS, THREADS, SMEM_BYTES>>>(theta, K, omega, Kg, mu,
                                         th_buf, coh_out);
}